// round 7
// baseline (speedup 1.0000x reference)
#include <cuda_runtime.h>

// Problem constants (shapes fixed by the dataset).
#define H_DIM 128
#define E_MAX 625000
#define N_MAX 100096

// Scratch (device globals — no allocations allowed).
// g_gate is read/written via float4 — must be 16B aligned (LD.128 traps otherwise).
__device__ __align__(16) float g_gate[E_MAX];
__device__ float        g_rowsum[N_MAX];
__device__ unsigned int g_h1[2048];
__device__ unsigned int g_h2[2048];
__device__ unsigned int g_h3[1024];
__device__ unsigned int g_sel1, g_sel2, g_sel3;
__device__ int          g_kRem;
__device__ int          g_idx32;   // 1 if edge_index is int32, 0 if int64

// Index fetch that works for either dtype (uniform branch on device flag).
__device__ __forceinline__ int edge_idx(const void* ei, int is32, long long pos) {
    if (is32) return ((const int*)ei)[pos];
    return (int)(((const long long*)ei)[pos]);
}

// ---------------------------------------------------------------------------
// K0: zero rowsum + histograms (graph replays reuse state, so zero each call).
// Block 0 additionally detects the edge_index dtype: if the buffer is int32,
// reading it as int64 yields idx0 + idx1*2^32 — out of [0,N) unless idx1==0
// (p ~ 1e-5 per sample). 1024 samples -> detection essentially certain.
// ---------------------------------------------------------------------------
__global__ void init_kernel(const void* ei, int N) {
    int i = blockIdx.x * blockDim.x + threadIdx.x;
    if (i < N)    g_rowsum[i] = 0.0f;
    if (i < 2048) { g_h1[i] = 0u; g_h2[i] = 0u; }
    if (i < 1024) g_h3[i] = 0u;

    if (blockIdx.x == 0) {               // block-uniform branch: sync is legal
        const long long* p = (const long long*)ei;
        int bad = 0;
        for (int j = threadIdx.x; j < 1024; j += blockDim.x) {
            long long v = p[j];
            if (v < 0 || v >= (long long)N) bad = 1;
        }
        int any = __syncthreads_or(bad);
        if (threadIdx.x == 0) g_idx32 = any ? 1 : 0;
    }
}

// ---------------------------------------------------------------------------
// K1: gate computation (warp per edge) + level-1 histogram (top 11 bits)
// ---------------------------------------------------------------------------
__global__ void gate_kernel(const float* __restrict__ x,
                            const void* __restrict__ ei,
                            const float* __restrict__ noise,
                            int E) {
    __shared__ unsigned int sh[2048];
    for (int i = threadIdx.x; i < 2048; i += blockDim.x) sh[i] = 0u;
    __syncthreads();

    const int is32   = g_idx32;
    const int lane   = threadIdx.x & 31;
    const int warpId = (blockIdx.x * blockDim.x + threadIdx.x) >> 5;
    const int nwarps = (gridDim.x * blockDim.x) >> 5;

    for (int e = warpId; e < E; e += nwarps) {
        int r = edge_idx(ei, is32, e);
        int c = edge_idx(ei, is32, (long long)E + e);
        float4 a = __ldg((const float4*)(x + ((long long)r << 7)) + lane);
        float4 b = __ldg((const float4*)(x + ((long long)c << 7)) + lane);
        float v = a.x * b.x;
        v = fmaf(a.y, b.y, v);
        v = fmaf(a.z, b.z, v);
        v = fmaf(a.w, b.w, v);
        #pragma unroll
        for (int off = 16; off > 0; off >>= 1)
            v += __shfl_down_sync(0xffffffffu, v, off);

        if (lane == 0) {
            float nz  = noise[e];
            // eps = (BIAS - (1-BIAS))*noise + (1-BIAS) = -0.9998*noise + 0.9999
            float eps = fmaf(-0.9998f, nz, 0.9999f);
            float ln  = logf(eps) - logf(1.0f - eps);
            float s   = (ln + v) * 2.0f;            // / TEMP_DE (0.5)
            float gate = 1.0f / (1.0f + expf(-s));
            g_gate[e] = gate;
            atomicAdd(&sh[__float_as_uint(gate) >> 21], 1u);
        }
    }
    __syncthreads();
    for (int i = threadIdx.x; i < 2048; i += blockDim.x)
        if (sh[i]) atomicAdd(&g_h1[i], sh[i]);
}

// ---------------------------------------------------------------------------
// Selection: single-block suffix-scan over a histogram, find bin containing
// the k-th largest element (descending). level selects in/out bindings.
// ---------------------------------------------------------------------------
__global__ void select_kernel(int level, int B, int k_in) {
    __shared__ unsigned int ssum[1024];
    const unsigned int* h = (level == 1) ? g_h1 : (level == 2) ? g_h2 : g_h3;
    int t = threadIdx.x;
    int per = (B > 1024) ? 2 : 1;

    unsigned int loc[2] = {0u, 0u};
    for (int j = 0; j < per; j++) loc[j] = h[t * per + j];
    ssum[t] = loc[0] + loc[1];
    __syncthreads();

    // Hillis-Steele inclusive suffix scan
    for (int off = 1; off < 1024; off <<= 1) {
        unsigned int v   = ssum[t];
        unsigned int add = (t + off < 1024) ? ssum[t + off] : 0u;
        __syncthreads();
        ssum[t] = v + add;
        __syncthreads();
    }

    unsigned int k = (unsigned int)((k_in >= 0) ? k_in : g_kRem);
    __syncthreads();   // all reads of g_kRem complete before the winner writes

    unsigned int nxt = (t + 1 < 1024) ? ssum[t + 1] : 0u;
    unsigned int run = nxt;
    for (int j = per - 1; j >= 0; j--) {
        unsigned int sfx = run + loc[j];
        if (sfx >= k && run < k) {
            unsigned int b = (unsigned int)(t * per + j);
            if (level == 1)      g_sel1 = b;
            else if (level == 2) g_sel2 = b;
            else                 g_sel3 = b;
            g_kRem = (int)(k - run);
        }
        run = sfx;
    }
}

// ---------------------------------------------------------------------------
// K3/K5: refinement histograms over gate bits (float4-vectorized sweeps)
// ---------------------------------------------------------------------------
__global__ void hist2_kernel(int E) {
    __shared__ unsigned int sh[2048];
    for (int i = threadIdx.x; i < 2048; i += blockDim.x) sh[i] = 0u;
    __syncthreads();
    unsigned int sel1 = g_sel1;
    int idx = blockIdx.x * blockDim.x + threadIdx.x;
    int stride = gridDim.x * blockDim.x;
    int nv = E >> 2;
    const float4* g4 = (const float4*)g_gate;
    for (int i = idx; i < nv; i += stride) {
        float4 g = g4[i];
        unsigned int u;
        u = __float_as_uint(g.x); if ((u >> 21) == sel1) atomicAdd(&sh[(u >> 10) & 0x7FFu], 1u);
        u = __float_as_uint(g.y); if ((u >> 21) == sel1) atomicAdd(&sh[(u >> 10) & 0x7FFu], 1u);
        u = __float_as_uint(g.z); if ((u >> 21) == sel1) atomicAdd(&sh[(u >> 10) & 0x7FFu], 1u);
        u = __float_as_uint(g.w); if ((u >> 21) == sel1) atomicAdd(&sh[(u >> 10) & 0x7FFu], 1u);
    }
    for (int e = (nv << 2) + idx; e < E; e += stride) {
        unsigned int u = __float_as_uint(g_gate[e]);
        if ((u >> 21) == sel1) atomicAdd(&sh[(u >> 10) & 0x7FFu], 1u);
    }
    __syncthreads();
    for (int i = threadIdx.x; i < 2048; i += blockDim.x)
        if (sh[i]) atomicAdd(&g_h2[i], sh[i]);
}

__global__ void hist3_kernel(int E) {
    __shared__ unsigned int sh[1024];
    for (int i = threadIdx.x; i < 1024; i += blockDim.x) sh[i] = 0u;
    __syncthreads();
    unsigned int pfx22 = (g_sel1 << 11) | g_sel2;
    int idx = blockIdx.x * blockDim.x + threadIdx.x;
    int stride = gridDim.x * blockDim.x;
    int nv = E >> 2;
    const float4* g4 = (const float4*)g_gate;
    for (int i = idx; i < nv; i += stride) {
        float4 g = g4[i];
        unsigned int u;
        u = __float_as_uint(g.x); if ((u >> 10) == pfx22) atomicAdd(&sh[u & 0x3FFu], 1u);
        u = __float_as_uint(g.y); if ((u >> 10) == pfx22) atomicAdd(&sh[u & 0x3FFu], 1u);
        u = __float_as_uint(g.z); if ((u >> 10) == pfx22) atomicAdd(&sh[u & 0x3FFu], 1u);
        u = __float_as_uint(g.w); if ((u >> 10) == pfx22) atomicAdd(&sh[u & 0x3FFu], 1u);
    }
    for (int e = (nv << 2) + idx; e < E; e += stride) {
        unsigned int u = __float_as_uint(g_gate[e]);
        if ((u >> 10) == pfx22) atomicAdd(&sh[u & 0x3FFu], 1u);
    }
    __syncthreads();
    for (int i = threadIdx.x; i < 1024; i += blockDim.x)
        if (sh[i]) atomicAdd(&g_h3[i], sh[i]);
}

// ---------------------------------------------------------------------------
// K7: apply threshold mask, scatter rowsum (vectorized, 4 edges/thread)
// ---------------------------------------------------------------------------
__global__ void scatter_kernel(const void* __restrict__ ei, int E) {
    unsigned int uT = (g_sel1 << 21) | (g_sel2 << 10) | g_sel3;
    const int is32 = g_idx32;
    int idx = blockIdx.x * blockDim.x + threadIdx.x;
    int stride = gridDim.x * blockDim.x;
    int nv = E >> 2;
    float4* g4 = (float4*)g_gate;

    for (int i = idx; i < nv; i += stride) {
        float4 g = g4[i];
        int r[4];
        if (is32) {
            int4 ri = ((const int4*)ei)[i];
            r[0] = ri.x; r[1] = ri.y; r[2] = ri.z; r[3] = ri.w;
        } else {
            longlong2 ra = ((const longlong2*)ei)[2 * i];
            longlong2 rb = ((const longlong2*)ei)[2 * i + 1];
            r[0] = (int)ra.x; r[1] = (int)ra.y; r[2] = (int)rb.x; r[3] = (int)rb.y;
        }
        float gv[4] = {g.x, g.y, g.z, g.w};
        bool changed = false;
        #pragma unroll
        for (int j = 0; j < 4; j++) {
            if (__float_as_uint(gv[j]) >= uT) {
                if (gv[j] != 0.0f) atomicAdd(&g_rowsum[r[j]], gv[j]);
            } else {
                gv[j] = 0.0f; changed = true;
            }
        }
        if (changed) {
            g4[i] = make_float4(gv[0], gv[1], gv[2], gv[3]);
        }
    }
    for (int e = (nv << 2) + idx; e < E; e += stride) {
        float gate = g_gate[e];
        if (__float_as_uint(gate) >= uT) {
            if (gate != 0.0f) atomicAdd(&g_rowsum[edge_idx(ei, is32, e)], gate);
        } else {
            g_gate[e] = 0.0f;
        }
    }
}

// ---------------------------------------------------------------------------
// K8: symmetric degree normalization -> output (vectorized, 4 edges/thread)
// ---------------------------------------------------------------------------
__device__ __forceinline__ float dinvf(float rs) {
    if (rs > 0.0f) return fminf(rsqrtf(rs), 10.0f);
    return 10.0f;
}

__global__ void out_kernel(const void* __restrict__ ei,
                           float* __restrict__ out, int E) {
    const int is32 = g_idx32;
    int idx = blockIdx.x * blockDim.x + threadIdx.x;
    int stride = gridDim.x * blockDim.x;
    int nv = E >> 2;
    const float4* g4 = (const float4*)g_gate;
    float4* o4 = (float4*)out;
    const long long co = (long long)E;  // col offset in elements

    for (int i = idx; i < nv; i += stride) {
        float4 g = g4[i];
        float gv[4] = {g.x, g.y, g.z, g.w};
        float ov[4];
        int r[4], c[4];
        if (is32) {
            int4 ri = ((const int4*)ei)[i];
            r[0] = ri.x; r[1] = ri.y; r[2] = ri.z; r[3] = ri.w;
            const int* cp = (const int*)ei + co;
            int4 ci = ((const int4*)cp)[i];
            c[0] = ci.x; c[1] = ci.y; c[2] = ci.z; c[3] = ci.w;
        } else {
            longlong2 ra = ((const longlong2*)ei)[2 * i];
            longlong2 rb = ((const longlong2*)ei)[2 * i + 1];
            r[0] = (int)ra.x; r[1] = (int)ra.y; r[2] = (int)rb.x; r[3] = (int)rb.y;
            const long long* cp = (const long long*)ei + co;
            longlong2 ca = ((const longlong2*)cp)[2 * i];
            longlong2 cb = ((const longlong2*)cp)[2 * i + 1];
            c[0] = (int)ca.x; c[1] = (int)ca.y; c[2] = (int)cb.x; c[3] = (int)cb.y;
        }
        #pragma unroll
        for (int j = 0; j < 4; j++) {
            float v = 0.0f;
            if (gv[j] != 0.0f) {
                float dr = dinvf(g_rowsum[r[j]]);
                float dc = dinvf(g_rowsum[c[j]]);
                v = gv[j] * dr * dc;
            }
            ov[j] = v;
        }
        o4[i] = make_float4(ov[0], ov[1], ov[2], ov[3]);
    }
    for (int e = (nv << 2) + idx; e < E; e += stride) {
        float g = g_gate[e];
        float v = 0.0f;
        if (g != 0.0f) {
            float dr = dinvf(g_rowsum[edge_idx(ei, is32, e)]);
            float dc = dinvf(g_rowsum[edge_idx(ei, is32, co + e)]);
            v = g * dr * dc;
        }
        out[e] = v;
    }
}

// ---------------------------------------------------------------------------
// Launcher
// ---------------------------------------------------------------------------
extern "C" void kernel_launch(void* const* d_in, const int* in_sizes, int n_in,
                              void* d_out, int out_size) {
    const float* x     = (const float*)d_in[0];
    const void*  ei    = d_in[1];
    const float* noise = (const float*)d_in[2];
    float*       out   = (float*)d_out;

    int E = in_sizes[2];
    int N = in_sizes[0] / H_DIM;

    int k = (int)((double)E * 0.8);   // matches python int(E * KEEP_FRAC)

    int initThreads = (N > 2048 ? N : 2048);
    init_kernel<<<(initThreads + 255) / 256, 256>>>(ei, N);

    gate_kernel<<<1184, 256>>>(x, ei, noise, E);
    select_kernel<<<1, 1024>>>(1, 2048, k);
    hist2_kernel<<<296, 256>>>(E);
    select_kernel<<<1, 1024>>>(2, 2048, -1);
    hist3_kernel<<<296, 256>>>(E);
    select_kernel<<<1, 1024>>>(3, 1024, -1);

    int vBlocks = ((E >> 2) + 255) / 256;
    scatter_kernel<<<vBlocks, 256>>>(ei, E);
    out_kernel<<<vBlocks, 256>>>(ei, out, E);
}

// round 10
// speedup vs baseline: 1.6488x; 1.6488x over previous
#include <cuda_runtime.h>

// Problem constants (shapes fixed by the dataset).
#define H_DIM 128
#define E_MAX 625000
#define N_MAX 100096

// Scratch (device globals — no allocations allowed).
// g_gate is read/written via float4 — must be 16B aligned (LD.128 traps otherwise).
__device__ __align__(16) float g_gate[E_MAX];
__device__ float        g_rowsum[N_MAX];
__device__ unsigned int g_h1[2048];
__device__ unsigned int g_h2[2048];
__device__ unsigned int g_h3[1024];
__device__ unsigned int g_sel1, g_sel2, g_sel3;
__device__ int          g_kRem;
__device__ int          g_idx32;   // 1 if edge_index is int32, 0 if int64

// Index fetch that works for either dtype (uniform branch on device flag).
__device__ __forceinline__ int edge_idx(const void* ei, int is32, long long pos) {
    if (is32) return ((const int*)ei)[pos];
    return (int)(((const long long*)ei)[pos]);
}

// ---------------------------------------------------------------------------
// K0: zero rowsum + histograms (graph replays reuse state, so zero each call).
// Block 0 additionally detects the edge_index dtype: if the buffer is int32,
// reading it as int64 yields idx0 + idx1*2^32 — out of [0,N) unless idx1==0
// (p ~ 1e-5 per sample). 1024 samples -> detection essentially certain.
// ---------------------------------------------------------------------------
__global__ void init_kernel(const void* ei, int N) {
    int i = blockIdx.x * blockDim.x + threadIdx.x;
    if (i < N)    g_rowsum[i] = 0.0f;
    if (i < 2048) { g_h1[i] = 0u; g_h2[i] = 0u; }
    if (i < 1024) g_h3[i] = 0u;

    if (blockIdx.x == 0) {               // block-uniform branch: sync is legal
        const long long* p = (const long long*)ei;
        int bad = 0;
        for (int j = threadIdx.x; j < 1024; j += blockDim.x) {
            long long v = p[j];
            if (v < 0 || v >= (long long)N) bad = 1;
        }
        int any = __syncthreads_or(bad);
        if (threadIdx.x == 0) g_idx32 = any ? 1 : 0;
    }
}

// ---------------------------------------------------------------------------
// K1: gate computation, 8 lanes per edge (4 edges/warp), + level-1 histogram.
//
// Math: with r = eps/(1-eps),
//   gate = sigmoid((log(eps)-log(1-eps) + w)/0.5) = sigmoid(2(ln r + w))
//        = r^2 / (r^2 + e^{-2w})
// Saturation ends (e^{-2w} -> 0 or inf) match the reference's sigmoid
// saturation; divergent edges are all in the dropped bottom 20% -> zeroed.
// ---------------------------------------------------------------------------
__global__ void gate_kernel(const float* __restrict__ x,
                            const void* __restrict__ ei,
                            const float* __restrict__ noise,
                            int E) {
    __shared__ unsigned int sh[2048];
    for (int i = threadIdx.x; i < 2048; i += blockDim.x) sh[i] = 0u;
    __syncthreads();

    const int is32 = g_idx32;
    const int lane = threadIdx.x & 31;
    const int sub  = lane >> 3;        // edge slot within warp (0..3)
    const int sl   = lane & 7;         // lane within 8-lane group
    const int warpId = (blockIdx.x * blockDim.x + threadIdx.x) >> 5;
    const int nwarps = (gridDim.x * blockDim.x) >> 5;

    for (int base = warpId << 2; base < E; base += nwarps << 2) {
        int e = base + sub;
        bool valid = (e < E);
        int ec = valid ? e : (E - 1);            // clamp for safe loads
        int r = edge_idx(ei, is32, ec);
        int c = edge_idx(ei, is32, (long long)E + ec);
        const float4* ra = (const float4*)(x + ((long long)r << 7));
        const float4* rb = (const float4*)(x + ((long long)c << 7));
        // 8 independent 16B loads in flight per lane (full 128-float row per 8 lanes)
        float4 a0 = __ldg(ra + sl);
        float4 a1 = __ldg(ra + sl + 8);
        float4 a2 = __ldg(ra + sl + 16);
        float4 a3 = __ldg(ra + sl + 24);
        float4 b0 = __ldg(rb + sl);
        float4 b1 = __ldg(rb + sl + 8);
        float4 b2 = __ldg(rb + sl + 16);
        float4 b3 = __ldg(rb + sl + 24);

        float v = a0.x * b0.x;
        v = fmaf(a0.y, b0.y, v); v = fmaf(a0.z, b0.z, v); v = fmaf(a0.w, b0.w, v);
        v = fmaf(a1.x, b1.x, v); v = fmaf(a1.y, b1.y, v); v = fmaf(a1.z, b1.z, v); v = fmaf(a1.w, b1.w, v);
        v = fmaf(a2.x, b2.x, v); v = fmaf(a2.y, b2.y, v); v = fmaf(a2.z, b2.z, v); v = fmaf(a2.w, b2.w, v);
        v = fmaf(a3.x, b3.x, v); v = fmaf(a3.y, b3.y, v); v = fmaf(a3.z, b3.z, v); v = fmaf(a3.w, b3.w, v);

        // reduce within the 8-lane group
        v += __shfl_xor_sync(0xffffffffu, v, 1);
        v += __shfl_xor_sync(0xffffffffu, v, 2);
        v += __shfl_xor_sync(0xffffffffu, v, 4);

        if (sl == 0 && valid) {
            float nz  = __ldg(noise + e);
            // eps = (BIAS - (1-BIAS))*noise + (1-BIAS) = -0.9998*noise + 0.9999
            float eps = fmaf(-0.9998f, nz, 0.9999f);
            float rr  = __fdividef(eps, 1.0f - eps);
            float r2  = rr * rr;
            float ex  = __expf(-2.0f * v);
            float gate = r2 / (r2 + ex);
            g_gate[e] = gate;
            atomicAdd(&sh[__float_as_uint(gate) >> 21], 1u);
        }
    }
    __syncthreads();
    for (int i = threadIdx.x; i < 2048; i += blockDim.x)
        if (sh[i]) atomicAdd(&g_h1[i], sh[i]);
}

// ---------------------------------------------------------------------------
// Selection: single-block suffix-scan over a histogram, find bin containing
// the k-th largest element (descending). level selects in/out bindings.
// ---------------------------------------------------------------------------
__global__ void select_kernel(int level, int B, int k_in) {
    __shared__ unsigned int ssum[1024];
    const unsigned int* h = (level == 1) ? g_h1 : (level == 2) ? g_h2 : g_h3;
    int t = threadIdx.x;
    int per = (B > 1024) ? 2 : 1;

    unsigned int loc[2] = {0u, 0u};
    for (int j = 0; j < per; j++) loc[j] = h[t * per + j];
    ssum[t] = loc[0] + loc[1];
    __syncthreads();

    // Hillis-Steele inclusive suffix scan
    for (int off = 1; off < 1024; off <<= 1) {
        unsigned int v   = ssum[t];
        unsigned int add = (t + off < 1024) ? ssum[t + off] : 0u;
        __syncthreads();
        ssum[t] = v + add;
        __syncthreads();
    }

    unsigned int k = (unsigned int)((k_in >= 0) ? k_in : g_kRem);
    __syncthreads();   // all reads of g_kRem complete before the winner writes

    unsigned int nxt = (t + 1 < 1024) ? ssum[t + 1] : 0u;
    unsigned int run = nxt;
    for (int j = per - 1; j >= 0; j--) {
        unsigned int sfx = run + loc[j];
        if (sfx >= k && run < k) {
            unsigned int b = (unsigned int)(t * per + j);
            if (level == 1)      g_sel1 = b;
            else if (level == 2) g_sel2 = b;
            else                 g_sel3 = b;
            g_kRem = (int)(k - run);
        }
        run = sfx;
    }
}

// ---------------------------------------------------------------------------
// K3/K5: refinement histograms over gate bits (float4-vectorized sweeps)
// ---------------------------------------------------------------------------
__global__ void hist2_kernel(int E) {
    __shared__ unsigned int sh[2048];
    for (int i = threadIdx.x; i < 2048; i += blockDim.x) sh[i] = 0u;
    __syncthreads();
    unsigned int sel1 = g_sel1;
    int idx = blockIdx.x * blockDim.x + threadIdx.x;
    int stride = gridDim.x * blockDim.x;
    int nv = E >> 2;
    const float4* g4 = (const float4*)g_gate;
    for (int i = idx; i < nv; i += stride) {
        float4 g = g4[i];
        unsigned int u;
        u = __float_as_uint(g.x); if ((u >> 21) == sel1) atomicAdd(&sh[(u >> 10) & 0x7FFu], 1u);
        u = __float_as_uint(g.y); if ((u >> 21) == sel1) atomicAdd(&sh[(u >> 10) & 0x7FFu], 1u);
        u = __float_as_uint(g.z); if ((u >> 21) == sel1) atomicAdd(&sh[(u >> 10) & 0x7FFu], 1u);
        u = __float_as_uint(g.w); if ((u >> 21) == sel1) atomicAdd(&sh[(u >> 10) & 0x7FFu], 1u);
    }
    for (int e = (nv << 2) + idx; e < E; e += stride) {
        unsigned int u = __float_as_uint(g_gate[e]);
        if ((u >> 21) == sel1) atomicAdd(&sh[(u >> 10) & 0x7FFu], 1u);
    }
    __syncthreads();
    for (int i = threadIdx.x; i < 2048; i += blockDim.x)
        if (sh[i]) atomicAdd(&g_h2[i], sh[i]);
}

__global__ void hist3_kernel(int E) {
    __shared__ unsigned int sh[1024];
    for (int i = threadIdx.x; i < 1024; i += blockDim.x) sh[i] = 0u;
    __syncthreads();
    unsigned int pfx22 = (g_sel1 << 11) | g_sel2;
    int idx = blockIdx.x * blockDim.x + threadIdx.x;
    int stride = gridDim.x * blockDim.x;
    int nv = E >> 2;
    const float4* g4 = (const float4*)g_gate;
    for (int i = idx; i < nv; i += stride) {
        float4 g = g4[i];
        unsigned int u;
        u = __float_as_uint(g.x); if ((u >> 10) == pfx22) atomicAdd(&sh[u & 0x3FFu], 1u);
        u = __float_as_uint(g.y); if ((u >> 10) == pfx22) atomicAdd(&sh[u & 0x3FFu], 1u);
        u = __float_as_uint(g.z); if ((u >> 10) == pfx22) atomicAdd(&sh[u & 0x3FFu], 1u);
        u = __float_as_uint(g.w); if ((u >> 10) == pfx22) atomicAdd(&sh[u & 0x3FFu], 1u);
    }
    for (int e = (nv << 2) + idx; e < E; e += stride) {
        unsigned int u = __float_as_uint(g_gate[e]);
        if ((u >> 10) == pfx22) atomicAdd(&sh[u & 0x3FFu], 1u);
    }
    __syncthreads();
    for (int i = threadIdx.x; i < 1024; i += blockDim.x)
        if (sh[i]) atomicAdd(&g_h3[i], sh[i]);
}

// ---------------------------------------------------------------------------
// K7: apply threshold mask, scatter rowsum (vectorized, 4 edges/thread)
// ---------------------------------------------------------------------------
__global__ void scatter_kernel(const void* __restrict__ ei, int E) {
    unsigned int uT = (g_sel1 << 21) | (g_sel2 << 10) | g_sel3;
    const int is32 = g_idx32;
    int idx = blockIdx.x * blockDim.x + threadIdx.x;
    int stride = gridDim.x * blockDim.x;
    int nv = E >> 2;
    float4* g4 = (float4*)g_gate;

    for (int i = idx; i < nv; i += stride) {
        float4 g = g4[i];
        int r[4];
        if (is32) {
            int4 ri = __ldg((const int4*)ei + i);
            r[0] = ri.x; r[1] = ri.y; r[2] = ri.z; r[3] = ri.w;
        } else {
            longlong2 ra = __ldg((const longlong2*)ei + 2 * i);
            longlong2 rb = __ldg((const longlong2*)ei + 2 * i + 1);
            r[0] = (int)ra.x; r[1] = (int)ra.y; r[2] = (int)rb.x; r[3] = (int)rb.y;
        }
        float gv[4] = {g.x, g.y, g.z, g.w};
        bool changed = false;
        #pragma unroll
        for (int j = 0; j < 4; j++) {
            if (__float_as_uint(gv[j]) >= uT) {
                if (gv[j] != 0.0f) atomicAdd(&g_rowsum[r[j]], gv[j]);
            } else {
                gv[j] = 0.0f; changed = true;
            }
        }
        if (changed) {
            g4[i] = make_float4(gv[0], gv[1], gv[2], gv[3]);
        }
    }
    for (int e = (nv << 2) + idx; e < E; e += stride) {
        float gate = g_gate[e];
        if (__float_as_uint(gate) >= uT) {
            if (gate != 0.0f) atomicAdd(&g_rowsum[edge_idx(ei, is32, e)], gate);
        } else {
            g_gate[e] = 0.0f;
        }
    }
}

// ---------------------------------------------------------------------------
// K8: symmetric degree normalization -> output (vectorized, 4 edges/thread)
// ---------------------------------------------------------------------------
__device__ __forceinline__ float dinvf(float rs) {
    if (rs > 0.0f) return fminf(rsqrtf(rs), 10.0f);
    return 10.0f;
}

__global__ void out_kernel(const void* __restrict__ ei,
                           float* __restrict__ out, int E) {
    const int is32 = g_idx32;
    int idx = blockIdx.x * blockDim.x + threadIdx.x;
    int stride = gridDim.x * blockDim.x;
    int nv = E >> 2;
    const float4* g4 = (const float4*)g_gate;
    float4* o4 = (float4*)out;
    const long long co = (long long)E;  // col offset in elements

    for (int i = idx; i < nv; i += stride) {
        float4 g = g4[i];
        float gv[4] = {g.x, g.y, g.z, g.w};
        float ov[4];
        int r[4], c[4];
        if (is32) {
            int4 ri = __ldg((const int4*)ei + i);
            r[0] = ri.x; r[1] = ri.y; r[2] = ri.z; r[3] = ri.w;
            const int* cp = (const int*)ei + co;
            int4 ci = __ldg((const int4*)cp + i);
            c[0] = ci.x; c[1] = ci.y; c[2] = ci.z; c[3] = ci.w;
        } else {
            longlong2 ra = __ldg((const longlong2*)ei + 2 * i);
            longlong2 rb = __ldg((const longlong2*)ei + 2 * i + 1);
            r[0] = (int)ra.x; r[1] = (int)ra.y; r[2] = (int)rb.x; r[3] = (int)rb.y;
            const long long* cp = (const long long*)ei + co;
            longlong2 ca = __ldg((const longlong2*)cp + 2 * i);
            longlong2 cb = __ldg((const longlong2*)cp + 2 * i + 1);
            c[0] = (int)ca.x; c[1] = (int)ca.y; c[2] = (int)cb.x; c[3] = (int)cb.y;
        }
        #pragma unroll
        for (int j = 0; j < 4; j++) {
            float v = 0.0f;
            if (gv[j] != 0.0f) {
                float dr = dinvf(g_rowsum[r[j]]);
                float dc = dinvf(g_rowsum[c[j]]);
                v = gv[j] * dr * dc;
            }
            ov[j] = v;
        }
        o4[i] = make_float4(ov[0], ov[1], ov[2], ov[3]);
    }
    for (int e = (nv << 2) + idx; e < E; e += stride) {
        float g = g_gate[e];
        float v = 0.0f;
        if (g != 0.0f) {
            float dr = dinvf(g_rowsum[edge_idx(ei, is32, e)]);
            float dc = dinvf(g_rowsum[edge_idx(ei, is32, co + e)]);
            v = g * dr * dc;
        }
        out[e] = v;
    }
}

// ---------------------------------------------------------------------------
// Launcher
// ---------------------------------------------------------------------------
extern "C" void kernel_launch(void* const* d_in, const int* in_sizes, int n_in,
                              void* d_out, int out_size) {
    const float* x     = (const float*)d_in[0];
    const void*  ei    = d_in[1];
    const float* noise = (const float*)d_in[2];
    float*       out   = (float*)d_out;

    int E = in_sizes[2];
    int N = in_sizes[0] / H_DIM;

    int k = (int)((double)E * 0.8);   // matches python int(E * KEEP_FRAC)

    int initThreads = (N > 2048 ? N : 2048);
    init_kernel<<<(initThreads + 255) / 256, 256>>>(ei, N);

    gate_kernel<<<1184, 256>>>(x, ei, noise, E);
    select_kernel<<<1, 1024>>>(1, 2048, k);
    hist2_kernel<<<888, 256>>>(E);
    select_kernel<<<1, 1024>>>(2, 2048, -1);
    hist3_kernel<<<888, 256>>>(E);
    select_kernel<<<1, 1024>>>(3, 1024, -1);

    int vBlocks = ((E >> 2) + 255) / 256;
    scatter_kernel<<<vBlocks, 256>>>(ei, E);
    out_kernel<<<vBlocks, 256>>>(ei, out, E);
}